// round 4
// baseline (speedup 1.0000x reference)
#include <cuda_runtime.h>
#include <stdint.h>

// ---------------------------------------------------------------------------
// Problem constants
// ---------------------------------------------------------------------------
#define Vn   10000
#define NBAT 4
#define NTT  12
#define NN   96          // 2 branches * 4 * 12
#define NH   3
#define NE   512
#define NS   32
#define ES   (NE*NS)     // 16384

// ---------------------------------------------------------------------------
// Device scratch (static allocation; no cudaMalloc allowed)
// ---------------------------------------------------------------------------
__device__ float g_Ft   [Vn * NN];        // transposed inputs F[v][n]
__device__ int   g_degi [NH * Vn];        // vertex degree per hypergraph
__device__ float g_rdeg [NH * Vn];        // 1 / max(deg,1)
__device__ float g_a1   [NH * NE * NN];   // layer-1 edge means
__device__ float g_s1   [NH * Vn * NN];   // layer-1 raw scatter sums
__device__ float g_m1   [NH * NE * NN];   // layer-2 edge means
__device__ float g_traw [NH * Vn * NN];   // layer-2 raw scatter sums
__device__ float g_T    [NN * Vn];        // attention-fused scalar field (t)
__device__ float g_P    [NN * Vn];        // attention-fused incidence field
__device__ float g_gc   [256];            // w_ih @ c
__device__ float g_gd   [256];            // w_ih @ d
__device__ float g_g0   [256];            // w_ih @ b2 + b_ih + b_hh
__device__ float g_whT  [64 * 256];       // w_hh re-laid-out [kin][kout][gate]
__device__ float g_sc   [6];              // CT, DT, BT, CB, DB, BB

// ---------------------------------------------------------------------------
// Kernel 0: zero scratch + init output to b_out
// ---------------------------------------------------------------------------
__global__ void k_zero(float* __restrict__ out, const float* __restrict__ b_out) {
    int i = blockIdx.x * 256 + threadIdx.x;   // grid covers NH*Vn*NN = 2,880,000
    g_s1[i]   = 0.f;
    g_traw[i] = 0.f;
    if (i < NH * Vn) g_degi[i] = 0;
    if (i < NBAT * Vn) out[i] = b_out[0];
}

// ---------------------------------------------------------------------------
// Kernel 1: precompute weight-derived constants (1 block, 256 threads)
// ---------------------------------------------------------------------------
__global__ void k_prep(const float* __restrict__ w1,     const float* __restrict__ b1,
                       const float* __restrict__ w2,     const float* __restrict__ b2,
                       const float* __restrict__ attn_w, const float* __restrict__ attn_a,
                       const float* __restrict__ w_ih,   const float* __restrict__ w_hh,
                       const float* __restrict__ b_ih,   const float* __restrict__ b_hh) {
    __shared__ float csh[64], dsh[64], cw[64], dw[64], bw[64];
    int t = threadIdx.x;

    if (t < 64) {
        float c = 0.f, d = 0.f;
        for (int i = 0; i < 64; i++) {
            float w = w2[i * 64 + t];
            c += w1[i] * w;
            d += b1[i] * w;
        }
        csh[t] = c; dsh[t] = d;
    }
    __syncthreads();

    if (t < 64) {
        float a = 0.f, b = 0.f, c = 0.f;
        for (int i = 0; i < 64; i++) {
            float w = attn_w[i * 64 + t];
            a += csh[i] * w;
            b += dsh[i] * w;
            c += b2[i]  * w;
        }
        cw[t] = a; dw[t] = b; bw[t] = c;
    }
    __syncthreads();

    if (t == 0) {
        float CT=0,DT=0,BT=0,CB=0,DB=0,BB=0;
        for (int j = 0; j < 64; j++) {
            float at = attn_a[j], ab = attn_a[64 + j];
            CT += cw[j]*at; DT += dw[j]*at; BT += bw[j]*at;
            CB += cw[j]*ab; DB += dw[j]*ab; BB += bw[j]*ab;
        }
        g_sc[0]=CT; g_sc[1]=DT; g_sc[2]=BT; g_sc[3]=CB; g_sc[4]=DB; g_sc[5]=BB;
    }

    // gc/gd/g0 for LSTM input projection (t in [0,256))
    {
        float a = 0.f, b = 0.f, c = 0.f;
        for (int k = 0; k < 64; k++) {
            float w = w_ih[t * 64 + k];
            a += w * csh[k];
            b += w * dsh[k];
            c += w * b2[k];
        }
        g_gc[t] = a;
        g_gd[t] = b;
        g_g0[t] = c + b_ih[t] + b_hh[t];
    }

    // Re-layout w_hh -> whT[kin*256 + kout*4 + gate] = w_hh[(gate*64+kout)*64 + kin]
    for (int idx = t; idx < 16384; idx += 256) {
        int kin = idx >> 8, r = idx & 255, kout = r >> 2, g = r & 3;
        g_whT[idx] = w_hh[(g * 64 + kout) * 64 + kin];
    }
}

// ---------------------------------------------------------------------------
// Kernel 2: transpose inputs into F[v][n]  (n = branch*48 + b*12 + t)
// ---------------------------------------------------------------------------
__global__ void k_transpose(const float* __restrict__ ten, const float* __restrict__ per) {
    int i = blockIdx.x * 256 + threadIdx.x;   // < Vn*NN
    int v = i / NN, n = i % NN;
    const float* src = (n < 48) ? ten : per;
    int nl = n % 48;
    g_Ft[i] = src[nl * Vn + v];
}

// ---------------------------------------------------------------------------
// Kernel 3: vertex degree per hypergraph
// ---------------------------------------------------------------------------
__global__ void k_deg(const int* __restrict__ edges) {
    int i = blockIdx.x * 256 + threadIdx.x;   // < NH*ES
    int h = i / ES;
    atomicAdd(&g_degi[h * Vn + edges[i]], 1);
}

__global__ void k_rdeg() {
    int i = blockIdx.x * 256 + threadIdx.x;
    if (i < NH * Vn) {
        int dg = g_degi[i];
        g_rdeg[i] = 1.0f / (float)(dg > 0 ? dg : 1);
    }
}

// ---------------------------------------------------------------------------
// Kernel 4: a1[h][e][n] = mean_s F[edges[h,e,s]][n]
// ---------------------------------------------------------------------------
__global__ void k_gather_a1(const int* __restrict__ edges) {
    int i = blockIdx.x * 256 + threadIdx.x;   // < NH*NE*NN = 147456
    int n = i % NN;
    int e = (i / NN) % NE;
    int h = i / (NN * NE);
    const int* ep = edges + (h * NE + e) * NS;
    float acc = 0.f;
    #pragma unroll
    for (int s = 0; s < NS; s++)
        acc += g_Ft[ep[s] * NN + n];
    g_a1[i] = acc * (1.0f / NS);
}

// ---------------------------------------------------------------------------
// Kernel 5: scatter a1 -> s1 raw sums
// ---------------------------------------------------------------------------
__global__ void k_scatter_s1(const int* __restrict__ edges) {
    int i = blockIdx.x * 256 + threadIdx.x;   // < NH*ES*NN = 4,718,592
    int n    = i % NN;
    int slot = (i / NN) % ES;
    int h    = i / (NN * ES);
    int v = edges[h * ES + slot];
    int e = slot >> 5;
    atomicAdd(&g_s1[(h * Vn + v) * NN + n], g_a1[(h * NE + e) * NN + n]);
}

// ---------------------------------------------------------------------------
// Kernel 6: m1[h][e][n] = mean_s ( s1[edges]/deg )
// ---------------------------------------------------------------------------
__global__ void k_gather_m1(const int* __restrict__ edges) {
    int i = blockIdx.x * 256 + threadIdx.x;   // < NH*NE*NN
    int n = i % NN;
    int e = (i / NN) % NE;
    int h = i / (NN * NE);
    const int* ep = edges + (h * NE + e) * NS;
    float acc = 0.f;
    #pragma unroll
    for (int s = 0; s < NS; s++) {
        int v = ep[s];
        acc += g_s1[(h * Vn + v) * NN + n] * g_rdeg[h * Vn + v];
    }
    g_m1[i] = acc * (1.0f / NS);
}

// ---------------------------------------------------------------------------
// Kernel 7: scatter m1 -> traw
// ---------------------------------------------------------------------------
__global__ void k_scatter_t(const int* __restrict__ edges) {
    int i = blockIdx.x * 256 + threadIdx.x;
    int n    = i % NN;
    int slot = (i / NN) % ES;
    int h    = i / (NN * ES);
    int v = edges[h * ES + slot];
    int e = slot >> 5;
    atomicAdd(&g_traw[(h * Vn + v) * NN + n], g_m1[(h * NE + e) * NN + n]);
}

// ---------------------------------------------------------------------------
// Kernel 8: attention over H=3 (scalar form) -> T, P fields
// ---------------------------------------------------------------------------
__global__ void k_attn() {
    int i = blockIdx.x * 256 + threadIdx.x;   // < NN*Vn, layout [n][v]
    int v = i % Vn;
    int n = i / Vn;

    float CT = g_sc[0], DT = g_sc[1], BT = g_sc[2];
    float CB = g_sc[3], DB = g_sc[4], BB = g_sc[5];

    float tv[NH], uf[NH];
    #pragma unroll
    for (int h = 0; h < NH; h++) {
        int idx = h * Vn + v;
        int dg = g_degi[idx];
        uf[h] = (dg > 0) ? 1.0f : 0.0f;
        tv[h] = g_traw[idx * NN + n] * g_rdeg[idx];
    }
    float tbar = (tv[0] + tv[1] + tv[2]) * (1.0f / 3.0f);
    float usum = uf[0] + uf[1] + uf[2];
    float zc = CB * tbar + BB + usum * (1.0f / 3.0f) * DB;

    float z[NH];
    #pragma unroll
    for (int h = 0; h < NH; h++) {
        float zz = CT * tv[h] + uf[h] * DT + BT + zc;
        z[h] = (zz > 0.f) ? zz : 0.2f * zz;     // leaky_relu(0.2)
    }
    float m = fmaxf(z[0], fmaxf(z[1], z[2]));
    float e0 = __expf(z[0] - m), e1 = __expf(z[1] - m), e2 = __expf(z[2] - m);
    float rden = 1.0f / (e0 + e1 + e2);
    g_T[i] = (e0 * tv[0] + e1 * tv[1] + e2 * tv[2]) * rden;
    g_P[i] = (e0 * uf[0] + e1 * uf[1] + e2 * uf[2]) * rden;
}

// ---------------------------------------------------------------------------
// Kernel 9: LSTM over 80000 independent sequences + final projection
//   block = 64 sequences, 256 threads
//   thread tile: 8 sequences x (2 k-outputs x 4 gates)
// ---------------------------------------------------------------------------
__device__ __forceinline__ float sigm(float x) { return 1.0f / (1.0f + __expf(-x)); }

extern __shared__ float smem[];

__global__ void __launch_bounds__(256) k_lstm(const float* __restrict__ w_out,
                                              float* __restrict__ out) {
    float* wsh   = smem;            // 16384 : w_hh [kin][kout][gate]
    float* hsh   = wsh   + 16384;   //  4096 : h [kin][seq]
    float* Tsh   = hsh   + 4096;    //   768 : T [t][seq]
    float* Psh   = Tsh   + 768;     //   768
    float* gcsh  = Psh   + 768;     //   256 : [kout][gate]
    float* gdsh  = gcsh  + 256;     //   256
    float* g0sh  = gdsh  + 256;     //   256
    float* outsh = g0sh  + 256;     //    64

    int tid = threadIdx.x;
    int st  = tid & 7;        // seq group: seqs st*8 .. st*8+7
    int kt  = tid >> 3;       // 0..31
    int k0  = kt * 2;         // output k pair
    int sb  = blockIdx.x * 64;

    // load shared
    for (int idx = tid; idx < 16384; idx += 256) wsh[idx] = g_whT[idx];
    {
        int kout = tid >> 2, g = tid & 3;
        gcsh[tid] = g_gc[g * 64 + kout];
        gdsh[tid] = g_gd[g * 64 + kout];
        g0sh[tid] = g_g0[g * 64 + kout];
    }
    if (tid < 64) outsh[tid] = 0.f;
    for (int idx = tid; idx < 768; idx += 256) {
        int s = idx & 63, t = idx >> 6;
        int sid = sb + s;
        int branch = sid / 40000;
        int rem = sid - branch * 40000;
        int b = rem / Vn;
        int v = rem - b * Vn;
        int n = branch * 48 + b * 12 + t;
        Tsh[t * 64 + s] = g_T[n * Vn + v];
        Psh[t * 64 + s] = g_P[n * Vn + v];
    }
    __syncthreads();

    float cst[8][2];
    #pragma unroll
    for (int ss = 0; ss < 8; ss++) { cst[ss][0] = 0.f; cst[ss][1] = 0.f; }

    float gcv[8], gdv[8], g0v[8];
    #pragma unroll
    for (int q = 0; q < 8; q++) {
        gcv[q] = gcsh[k0 * 4 + q];
        gdv[q] = gdsh[k0 * 4 + q];
        g0v[q] = g0sh[k0 * 4 + q];
    }

    for (int t = 0; t < NTT; t++) {
        float acc[8][8];
        #pragma unroll
        for (int ss = 0; ss < 8; ss++) {
            float Tt = Tsh[t * 64 + st * 8 + ss];
            float Pt = Psh[t * 64 + st * 8 + ss];
            #pragma unroll
            for (int q = 0; q < 8; q++)
                acc[ss][q] = fmaf(Tt, gcv[q], fmaf(Pt, gdv[q], g0v[q]));
        }

        if (t > 0) {
            #pragma unroll 4
            for (int kin = 0; kin < 64; kin++) {
                float4 ha = *(const float4*)&hsh[kin * 64 + st * 8];
                float4 hb = *(const float4*)&hsh[kin * 64 + st * 8 + 4];
                float4 wa = *(const float4*)&wsh[kin * 256 + k0 * 4];
                float4 wb = *(const float4*)&wsh[kin * 256 + k0 * 4 + 4];
                float hv[8] = {ha.x, ha.y, ha.z, ha.w, hb.x, hb.y, hb.z, hb.w};
                float wv[8] = {wa.x, wa.y, wa.z, wa.w, wb.x, wb.y, wb.z, wb.w};
                #pragma unroll
                for (int ss = 0; ss < 8; ss++)
                    #pragma unroll
                    for (int q = 0; q < 8; q++)
                        acc[ss][q] = fmaf(hv[ss], wv[q], acc[ss][q]);
            }
        }
        __syncthreads();   // all hsh reads done before rewrite

        #pragma unroll
        for (int ss = 0; ss < 8; ss++) {
            #pragma unroll
            for (int kk = 0; kk < 2; kk++) {
                float gi = acc[ss][kk * 4 + 0];
                float gf = acc[ss][kk * 4 + 1];
                float gg = acc[ss][kk * 4 + 2];
                float go = acc[ss][kk * 4 + 3];
                float cn = sigm(gf) * cst[ss][kk] + sigm(gi) * tanhf(gg);
                cst[ss][kk] = cn;
                float hn = sigm(go) * tanhf(cn);
                hsh[(k0 + kk) * 64 + st * 8 + ss] = hn;
            }
        }
        __syncthreads();   // new h visible
    }

    // final projection: out[b*V+v] += h . w_out[branch*64 : +64]
    int branch = sb / 40000;               // uniform per block (40000 % 64 == 0)
    float wo0 = w_out[branch * 64 + k0];
    float wo1 = w_out[branch * 64 + k0 + 1];
    #pragma unroll
    for (int ss = 0; ss < 8; ss++) {
        int s = st * 8 + ss;
        float p = hsh[k0 * 64 + s] * wo0 + hsh[(k0 + 1) * 64 + s] * wo1;
        atomicAdd(&outsh[s], p);
    }
    __syncthreads();
    if (tid < 64) {
        int sid = sb + tid;
        int rem = sid % 40000;             // = b*V + v
        atomicAdd(&out[rem], outsh[tid]);
    }
}

// ---------------------------------------------------------------------------
// Host launch
// ---------------------------------------------------------------------------
extern "C" void kernel_launch(void* const* d_in, const int* in_sizes, int n_in,
                              void* d_out, int out_size) {
    const float* tendency    = (const float*)d_in[0];
    const float* periodicity = (const float*)d_in[1];
    const int*   edges       = (const int*)  d_in[2];
    const float* w1          = (const float*)d_in[3];
    const float* b1          = (const float*)d_in[4];
    const float* w2          = (const float*)d_in[5];
    const float* b2          = (const float*)d_in[6];
    const float* attn_w      = (const float*)d_in[7];
    const float* attn_a      = (const float*)d_in[8];
    const float* w_ih        = (const float*)d_in[9];
    const float* w_hh        = (const float*)d_in[10];
    const float* b_ih        = (const float*)d_in[11];
    const float* b_hh        = (const float*)d_in[12];
    const float* w_out       = (const float*)d_in[13];
    const float* b_out       = (const float*)d_in[14];
    float* out = (float*)d_out;

    cudaFuncSetAttribute(k_lstm, cudaFuncAttributeMaxDynamicSharedMemorySize, 91392);

    k_zero      <<<11250, 256>>>(out, b_out);
    k_prep      <<<1,     256>>>(w1, b1, w2, b2, attn_w, attn_a, w_ih, w_hh, b_ih, b_hh);
    k_transpose <<<3750,  256>>>(tendency, periodicity);
    k_deg       <<<(NH * ES) / 256, 256>>>(edges);           // 192 blocks
    k_rdeg      <<<(NH * Vn + 255) / 256, 256>>>();
    k_gather_a1 <<<(NH * NE * NN) / 256, 256>>>(edges);      // 576
    k_scatter_s1<<<(NH * ES * NN) / 256, 256>>>(edges);      // 18432
    k_gather_m1 <<<(NH * NE * NN) / 256, 256>>>(edges);
    k_scatter_t <<<(NH * ES * NN) / 256, 256>>>(edges);
    k_attn      <<<3750,  256>>>();
    k_lstm      <<<1250,  256, 91392>>>(w_out, out);
}